// round 15
// baseline (speedup 1.0000x reference)
#include <cuda_runtime.h>
#include <math.h>
#include <stdint.h>

// Problem constants
#define B_   4
#define L_   2048
#define D_   1024
#define H_   16
#define HD_  64
#define BH_  (B_*H_)
#define BL_  (B_*L_)
#define SCALE_ 0.125f   // 1/sqrt(64)
#define LOG2E_ 1.4426950408889634f

// ---------------- scratch (device globals; no allocation allowed) ----------
__device__ float g_qa [BL_ * D_];          // q_in, tf32 + k-interleaved
__device__ float g_ka [BL_ * D_];          // k_in, tf32 + k-interleaved
__device__ float g_wq [D_ * D_];           // Wq,  tf32, rows k-interleaved
__device__ float g_wkv[D_ * 2 * D_];       // Wkv, tf32, rows k-interleaved
__device__ float g_wp [D_ * D_];           // Wp,  tf32, rows k-interleaved
__device__ float g_qp [BL_ * D_];          // q projection  [b*l][1024] fp32
__device__ float g_kvp[BL_ * 2 * D_];      // kv projection [b*l][2048] fp32
__device__ float g_q  [BH_ * L_ * HD_];    // [b,h,l,hd(interleaved)] tf32 bits
__device__ float g_k  [BH_ * L_ * HD_];    // [b,h,l,hd(interleaved)] tf32 bits
__device__ float g_vt [BH_ * HD_ * L_];    // [b,h,hd,l] transposed, tf32 bits
__device__ float g_attn[BL_ * D_];         // [b,l,h*hd] tf32 + k-interleaved

// ---------------- tf32 helpers ---------------------------------------------
__device__ __forceinline__ uint32_t f2tf(float f) {
    uint32_t r;
    asm("cvt.rna.tf32.f32 %0, %1;" : "=r"(r) : "f"(f));
    return r;
}
__device__ __forceinline__ float f2tf_f(float f) {
    return __uint_as_float(f2tf(f));
}
__device__ __forceinline__ float ex2(float x) {
    float r;
    asm("ex2.approx.f32 %0, %1;" : "=f"(r) : "f"(x));
    return r;
}

__device__ __forceinline__ void mma_tf32(float* d, const uint32_t* a, const uint32_t* b) {
    asm volatile(
        "mma.sync.aligned.m16n8k8.row.col.f32.tf32.tf32.f32 "
        "{%0,%1,%2,%3}, {%4,%5,%6,%7}, {%8,%9}, {%0,%1,%2,%3};"
        : "+f"(d[0]), "+f"(d[1]), "+f"(d[2]), "+f"(d[3])
        : "r"(a[0]), "r"(a[1]), "r"(a[2]), "r"(a[3]), "r"(b[0]), "r"(b[1]));
}

__device__ __forceinline__ void cp16(uint32_t smem_addr, const void* gptr) {
    asm volatile("cp.async.cg.shared.global [%0], [%1], 16;" :: "r"(smem_addr), "l"(gptr));
}
#define CP_COMMIT() asm volatile("cp.async.commit_group;")
#define CP_WAIT0()  asm volatile("cp.async.wait_group 0;")
#define CP_WAIT1()  asm volatile("cp.async.wait_group 1;")

// within-8 interleave: logical w -> phys ((w&3)<<1)|(w>>2)   (phys 2t <- logical t)
__device__ __forceinline__ int ilv(int j) {
    int w = j & 7;
    return (j & ~7) | (((w & 3) << 1) | (w >> 2));
}

// ---------------- pre-convert kernels --------------------------------------
// A matrices: fp32 -> tf32, interleave cols within groups of 8. y=0: q, y=1: k.
__global__ void __launch_bounds__(256) conv_a_kernel(
    const float* __restrict__ in0, float* __restrict__ out0,
    const float* __restrict__ in1, float* __restrict__ out1)
{
    const float* in  = blockIdx.y ? in1 : in0;
    float* out       = blockIdx.y ? out1 : out0;
    int idx = blockIdx.x * 256 + threadIdx.x;   // one per 8 cols
    const float4* ip = (const float4*)in + (size_t)idx * 2;
    float4 a = ip[0], b = ip[1];
    float4 o0 = make_float4(f2tf_f(a.x), f2tf_f(b.x), f2tf_f(a.y), f2tf_f(b.y));
    float4 o1 = make_float4(f2tf_f(a.z), f2tf_f(b.z), f2tf_f(a.w), f2tf_f(b.w));
    float4* op = (float4*)out + (size_t)idx * 2;
    op[0] = o0; op[1] = o1;
}

// W matrices: fp32 -> tf32, permute rows within groups of 8.
__global__ void __launch_bounds__(256) conv_w_kernel(
    const float* __restrict__ in, float* __restrict__ out, int N)
{
    int idx = blockIdx.x * 256 + threadIdx.x;   // one float4
    int n4 = N >> 2;
    int k = idx / n4;
    int c = (idx - k * n4) << 2;
    int kp = ilv(k);
    float4 v = *(const float4*)(in + (size_t)k * N + c);
    *(float4*)(out + (size_t)kp * N + c) =
        make_float4(f2tf_f(v.x), f2tf_f(v.y), f2tf_f(v.z), f2tf_f(v.w));
}

// ---------------- TF32 GEMM v3 ---------------------------------------------
// C[M,N] = A[M,K] @ W[K,N] + bias. A,W already tf32 + k-interleaved.
// 128x128 block, BK=32, 128 threads (4 warps, 2x2, 64x64 warp tile).
// 3-stage cp.async pipeline.
#define GAS 40    // A smem row stride (words)
#define GBS 132   // B smem row stride (words)
#define GA_WORDS (128 * GAS)          // 5120
#define GB_WORDS (32 * GBS)           // 4224
#define GSTAGE   (GA_WORDS + GB_WORDS)
#define GSMEM    (3 * GSTAGE * 4)     // 112128 bytes

__global__ void __launch_bounds__(128) gemm_tf32_kernel(
    const float* __restrict__ A, const float* __restrict__ W,
    const float* __restrict__ bias, float* __restrict__ C,
    int M, int N, int K)
{
    extern __shared__ uint32_t smg[];

    const int tid = threadIdx.x;
    const int lane = tid & 31;
    const int wid = tid >> 5;
    const int g = lane >> 2, t = lane & 3;
    const int m0 = blockIdx.y << 7, n0 = blockIdx.x << 7;
    const int wm = (wid & 1) << 6;   // 0 or 64
    const int wn = (wid >> 1) << 6;  // 0 or 64

    float acc[4][8][4];
#pragma unroll
    for (int i = 0; i < 4; i++)
#pragma unroll
        for (int j = 0; j < 8; j++)
#pragma unroll
            for (int e = 0; e < 4; e++) acc[i][j][e] = 0.f;

    // loader mapping (128 threads)
    const int ar = tid >> 3;             // 0..15 (+16 per u, 8 u)
    const int ac4 = (tid & 7) << 2;      // 0..28
    const int bk = tid >> 5;             // 0..3 (+4 per u, 8 u)
    const int bc4 = (tid & 31) << 2;     // 0..124

    const uint32_t sbase = (uint32_t)__cvta_generic_to_shared(smg);
    const int NT = K >> 5;

    // prologue: issue tiles 0 and 1
#pragma unroll
    for (int pt = 0; pt < 2; pt++) {
        const int kt = pt << 5;
        uint32_t sa = sbase + pt * (GSTAGE * 4);
        uint32_t sb = sa + GA_WORDS * 4;
#pragma unroll
        for (int u = 0; u < 8; u++) {
            int r = ar + (u << 4);
            cp16(sa + (uint32_t)(r * GAS + ac4) * 4, A + (size_t)(m0 + r) * K + kt + ac4);
        }
#pragma unroll
        for (int u = 0; u < 8; u++) {
            int r = bk + (u << 2);
            cp16(sb + (uint32_t)(r * GBS + bc4) * 4, W + (size_t)(kt + r) * N + n0 + bc4);
        }
        CP_COMMIT();
    }

    int cur = 0, nxt = 2;
    for (int ti = 0; ti < NT; ti++) {
        if (ti + 1 < NT) { CP_WAIT1(); } else { CP_WAIT0(); }
        __syncthreads();

        // issue tile ti+2 into stage nxt
        if (ti + 2 < NT) {
            const int kt = (ti + 2) << 5;
            uint32_t sa = sbase + nxt * (GSTAGE * 4);
            uint32_t sb = sa + GA_WORDS * 4;
#pragma unroll
            for (int u = 0; u < 8; u++) {
                int r = ar + (u << 4);
                cp16(sa + (uint32_t)(r * GAS + ac4) * 4, A + (size_t)(m0 + r) * K + kt + ac4);
            }
#pragma unroll
            for (int u = 0; u < 8; u++) {
                int r = bk + (u << 2);
                cp16(sb + (uint32_t)(r * GBS + bc4) * 4, W + (size_t)(kt + r) * N + n0 + bc4);
            }
            CP_COMMIT();
        }

        const uint32_t* a_ = smg + cur * GSTAGE;
        const uint32_t* b_ = a_ + GA_WORDS;

#pragma unroll
        for (int kf = 0; kf < 4; kf++) {
            const int k0 = kf << 3;
            uint32_t af[4][4];
#pragma unroll
            for (int mf = 0; mf < 4; mf++) {
                const int r = wm + (mf << 4) + g;
                uint2 p0 = *(const uint2*)&a_[r * GAS + k0 + 2 * t];
                uint2 p1 = *(const uint2*)&a_[(r + 8) * GAS + k0 + 2 * t];
                af[mf][0] = p0.x; af[mf][1] = p1.x; af[mf][2] = p0.y; af[mf][3] = p1.y;
            }
            uint32_t bf[8][2];
#pragma unroll
            for (int nf = 0; nf < 8; nf++) {
                const int c = wn + (nf << 3) + g;
                bf[nf][0] = b_[(k0 + 2 * t) * GBS + c];
                bf[nf][1] = b_[(k0 + 2 * t + 1) * GBS + c];
            }
#pragma unroll
            for (int mf = 0; mf < 4; mf++)
#pragma unroll
                for (int nf = 0; nf < 8; nf++)
                    mma_tf32(acc[mf][nf], af[mf], bf[nf]);
        }
        cur = (cur + 1 == 3) ? 0 : cur + 1;
        nxt = (nxt + 1 == 3) ? 0 : nxt + 1;
    }

    // epilogue (logical n, no interleave)
#pragma unroll
    for (int nf = 0; nf < 8; nf++) {
        const int col = n0 + wn + (nf << 3) + (t << 1);
        const float b0 = bias[col], b1 = bias[col + 1];
#pragma unroll
        for (int mf = 0; mf < 4; mf++) {
            const int row0 = m0 + wm + (mf << 4) + g;
            *(float2*)&C[(size_t)row0 * N + col] =
                make_float2(acc[mf][nf][0] + b0, acc[mf][nf][1] + b1);
            *(float2*)&C[(size_t)(row0 + 8) * N + col] =
                make_float2(acc[mf][nf][2] + b0, acc[mf][nf][3] + b1);
        }
    }
}

// ---------------- RoPE + head split + V transpose (all outputs tf32) -------
__global__ void __launch_bounds__(256) rope_split_kernel(const float* __restrict__ rope)
{
    __shared__ float sv[64][65];

    const int tid = threadIdx.x;
    const int l0 = blockIdx.x << 6;
    const int bh = blockIdx.y;
    const int b = bh >> 4, h = bh & 15;

    const int p = tid & 31;
    const int lr = (tid >> 5) << 3;

    const int j0 = ilv(2 * p);
    const int j1 = ilv(2 * p + 1);

#pragma unroll
    for (int u = 0; u < 8; u++) {
        const int l = lr + u;
        float2 rp = ((const float2*)rope)[(l0 + l) * 32 + p];
        const float sn = rp.x, cs = rp.y;

        const size_t rowq = (size_t)(b * L_ + l0 + l);
        float2 q = ((const float2*)g_qp)[rowq * 512 + h * 32 + p];
        const size_t kvb = rowq * 1024;
        float2 k = ((const float2*)g_kvp)[kvb + h * 32 + p];
        float2 v = ((const float2*)g_kvp)[kvb + 512 + h * 32 + p];

        float qe = q.x * cs - q.y * sn, qo = q.x * sn + q.y * cs;
        float ke = k.x * cs - k.y * sn, ko = k.x * sn + k.y * cs;

        const size_t ob = (size_t)(bh * L_ + l0 + l) * 64;
        g_q[ob + j0] = f2tf_f(qe);
        g_q[ob + j1] = f2tf_f(qo);
        g_k[ob + j0] = f2tf_f(ke);
        g_k[ob + j1] = f2tf_f(ko);

        sv[l][2 * p]     = v.x;
        sv[l][2 * p + 1] = v.y;
    }
    __syncthreads();

    const int hd = tid >> 2;
    const int c0 = (tid & 3) << 4;
    float* dst = g_vt + ((size_t)bh * 64 + hd) * L_ + l0 + c0;
#pragma unroll
    for (int j4 = 0; j4 < 4; j4++) {
        float4 o;
        o.x = f2tf_f(sv[c0 + j4 * 4 + 0][hd]);
        o.y = f2tf_f(sv[c0 + j4 * 4 + 1][hd]);
        o.z = f2tf_f(sv[c0 + j4 * 4 + 2][hd]);
        o.w = f2tf_f(sv[c0 + j4 * 4 + 3][hd]);
        *(float4*)(dst + j4 * 4) = o;
    }
}

// ---------------- causal flash attention (tf32 mma, cp.async pipelined) ----
#define FS 72
#define FTILE (64 * FS)
#define FSMEM (4 * FTILE * 4)

__global__ void __launch_bounds__(128) flash_tc_kernel()
{
    extern __shared__ float smf[];
    float* bufK[2] = { smf,             smf + 2 * FTILE };
    float* bufV[2] = { smf + FTILE,     smf + 3 * FTILE };

    const int tid = threadIdx.x;
    const int lane = tid & 31;
    const int wid = tid >> 5;
    const int g = lane >> 2, t = lane & 3;
    const int bh = blockIdx.x;
    const int qb = 31 - blockIdx.y;     // heavy blocks first
    const int q0 = qb * 64;
    const int b = bh >> 4, h = bh & 15;
    const int mrow = wid << 4;

    const float* Qg = g_q + ((size_t)bh * L_ + q0) * HD_;
    const float* Kg = g_k + (size_t)bh * L_ * HD_;
    const float* Vt = g_vt + (size_t)bh * HD_ * L_;

    const int cr = tid >> 4;
    const int cc4 = (tid & 15) << 2;

    {
        uint32_t skb = (uint32_t)__cvta_generic_to_shared(bufK[0]);
        uint32_t svb = (uint32_t)__cvta_generic_to_shared(bufV[0]);
#pragma unroll
        for (int u = 0; u < 8; u++) {
            int r = cr + (u << 3);
            cp16(skb + (uint32_t)(r * FS + cc4) * 4, Kg + (size_t)r * 64 + cc4);
            cp16(svb + (uint32_t)(r * FS + cc4) * 4, Vt + (size_t)r * L_ + cc4);
        }
        CP_COMMIT();
    }

    // stage Q into buf1 K region
#pragma unroll
    for (int u = 0; u < 8; u++) {
        int idx = tid + (u << 7);
        int r = idx >> 4;
        int c4 = (idx & 15) << 2;
        *(float4*)&bufK[1][r * FS + c4] = *(const float4*)(Qg + (size_t)r * 64 + c4);
    }
    __syncthreads();

    uint32_t qf[8][4];
#pragma unroll
    for (int kf = 0; kf < 8; kf++) {
        uint2 p0 = *(const uint2*)&bufK[1][(mrow + g) * FS + (kf << 3) + 2 * t];
        uint2 p1 = *(const uint2*)&bufK[1][(mrow + g + 8) * FS + (kf << 3) + 2 * t];
        qf[kf][0] = p0.x; qf[kf][1] = p1.x; qf[kf][2] = p0.y; qf[kf][3] = p1.y;
    }

    float Of[8][4];
    float m_i[2] = {-INFINITY, -INFINITY};
    float l_i[2] = {0.f, 0.f};
#pragma unroll
    for (int nf = 0; nf < 8; nf++)
#pragma unroll
        for (int e = 0; e < 4; e++) Of[nf][e] = 0.f;

    const float SC2 = SCALE_ * LOG2E_;
    int cur = 0;

    for (int kb = 0; kb <= qb; kb++) {
        CP_WAIT0();
        __syncthreads();

        if (kb < qb) {
            const int nn = (kb + 1) * 64;
            uint32_t skb = (uint32_t)__cvta_generic_to_shared(bufK[cur ^ 1]);
            uint32_t svb = (uint32_t)__cvta_generic_to_shared(bufV[cur ^ 1]);
#pragma unroll
            for (int u = 0; u < 8; u++) {
                int r = cr + (u << 3);
                cp16(skb + (uint32_t)(r * FS + cc4) * 4, Kg + (size_t)(nn + r) * 64 + cc4);
                cp16(svb + (uint32_t)(r * FS + cc4) * 4, Vt + (size_t)r * L_ + nn + cc4);
            }
            CP_COMMIT();
        }

        const uint32_t* sK = (const uint32_t*)bufK[cur];
        const uint32_t* sV = (const uint32_t*)bufV[cur];
        const int n0 = kb * 64;

        // S = Q K^T  (kf outer -> 8 independent accumulator chains)
        float Sf[8][4];
#pragma unroll
        for (int nf = 0; nf < 8; nf++)
#pragma unroll
            for (int e = 0; e < 4; e++) Sf[nf][e] = 0.f;

#pragma unroll
        for (int kf = 0; kf < 8; kf++) {
            const uint32_t* kbase = sK + (kf << 3) + 2 * t;
#pragma unroll
            for (int nf = 0; nf < 8; nf++) {
                uint2 bv = *(const uint2*)(kbase + ((nf << 3) + g) * FS);
                uint32_t bfr[2] = { bv.x, bv.y };
                mma_tf32(Sf[nf], qf[kf], bfr);
            }
        }

        const int row0 = q0 + mrow + g;
        const int row1 = row0 + 8;
        const bool diag = (kb == qb);
#pragma unroll
        for (int nf = 0; nf < 8; nf++) {
            Sf[nf][0] *= SC2; Sf[nf][1] *= SC2;
            Sf[nf][2] *= SC2; Sf[nf][3] *= SC2;
            if (diag) {
                const int c0 = n0 + (nf << 3) + 2 * t;
                if (c0 > row0)     Sf[nf][0] = -1e9f;
                if (c0 + 1 > row0) Sf[nf][1] = -1e9f;
                if (c0 > row1)     Sf[nf][2] = -1e9f;
                if (c0 + 1 > row1) Sf[nf][3] = -1e9f;
            }
        }

        float rm0 = -INFINITY, rm1 = -INFINITY;
#pragma unroll
        for (int nf = 0; nf < 8; nf++) {
            rm0 = fmaxf(rm0, fmaxf(Sf[nf][0], Sf[nf][1]));
            rm1 = fmaxf(rm1, fmaxf(Sf[nf][2], Sf[nf][3]));
        }
        rm0 = fmaxf(rm0, __shfl_xor_sync(0xffffffffu, rm0, 1));
        rm0 = fmaxf(rm0, __shfl_xor_sync(0xffffffffu, rm0, 2));
        rm1 = fmaxf(rm1, __shfl_xor_sync(0xffffffffu, rm1, 1));
        rm1 = fmaxf(rm1, __shfl_xor_sync(0xffffffffu, rm1, 2));

        const float mn0 = fmaxf(m_i[0], rm0);
        const float mn1 = fmaxf(m_i[1], rm1);
        const float corr0 = ex2(m_i[0] - mn0);
        const float corr1 = ex2(m_i[1] - mn1);
        m_i[0] = mn0; m_i[1] = mn1;

        uint32_t pa[8][4];
        float ps0 = 0.f, ps1 = 0.f;
#pragma unroll
        for (int nf = 0; nf < 8; nf++) {
            float p0 = ex2(Sf[nf][0] - mn0);
            float p1 = ex2(Sf[nf][1] - mn0);
            float p2 = ex2(Sf[nf][2] - mn1);
            float p3 = ex2(Sf[nf][3] - mn1);
            ps0 += p0 + p1;
            ps1 += p2 + p3;
            pa[nf][0] = f2tf(p0); pa[nf][1] = f2tf(p2);
            pa[nf][2] = f2tf(p1); pa[nf][3] = f2tf(p3);
        }
        ps0 += __shfl_xor_sync(0xffffffffu, ps0, 1);
        ps0 += __shfl_xor_sync(0xffffffffu, ps0, 2);
        ps1 += __shfl_xor_sync(0xffffffffu, ps1, 1);
        ps1 += __shfl_xor_sync(0xffffffffu, ps1, 2);
        l_i[0] = l_i[0] * corr0 + ps0;
        l_i[1] = l_i[1] * corr1 + ps1;

#pragma unroll
        for (int nf = 0; nf < 8; nf++) {
            Of[nf][0] *= corr0; Of[nf][1] *= corr0;
            Of[nf][2] *= corr1; Of[nf][3] *= corr1;
        }

        // O += P @ V  (pc outer -> independent chains across onf)
#pragma unroll
        for (int pc = 0; pc < 8; pc++) {
#pragma unroll
            for (int onf = 0; onf < 8; onf++) {
                uint2 vv = *(const uint2*)(sV + ((onf << 3) + g) * FS + (pc << 3) + 2 * t);
                uint32_t bfr[2] = { vv.x, vv.y };
                mma_tf32(Of[onf], pa[pc], bfr);
            }
        }
        cur ^= 1;
    }

    // normalize + write g_attn as tf32 + k-interleaved (for out-proj GEMM)
    const float inv0 = 1.f / l_i[0];
    const float inv1 = 1.f / l_i[1];
    const int row0 = q0 + mrow + g;
    const int row1 = row0 + 8;
    const int pc0 = ((t & 1) << 2) | (t >> 1);   // phys(2t): {0,4,1,5}
#pragma unroll
    for (int nf = 0; nf < 8; nf++) {
        const int basec = h * HD_ + (nf << 3);
        g_attn[(size_t)(b * L_ + row0) * D_ + basec + pc0]     = f2tf_f(Of[nf][0] * inv0);
        g_attn[(size_t)(b * L_ + row0) * D_ + basec + pc0 + 2] = f2tf_f(Of[nf][1] * inv0);
        g_attn[(size_t)(b * L_ + row1) * D_ + basec + pc0]     = f2tf_f(Of[nf][2] * inv1);
        g_attn[(size_t)(b * L_ + row1) * D_ + basec + pc0 + 2] = f2tf_f(Of[nf][3] * inv1);
    }
}

// ---------------- launch ----------------------------------------------------
extern "C" void kernel_launch(void* const* d_in, const int* in_sizes, int n_in,
                              void* d_out, int out_size)
{
    const float* q_in = (const float*)d_in[0];
    const float* k_in = (const float*)d_in[1];
    // d_in[2] = v_in (unused by reference), d_in[3] = mask (tril, hardcoded causal)
    const float* rope = (const float*)d_in[4];
    const float* Wq   = (const float*)d_in[5];
    const float* bq   = (const float*)d_in[6];
    const float* Wkv  = (const float*)d_in[7];
    const float* bkv  = (const float*)d_in[8];
    const float* Wp   = (const float*)d_in[9];
    const float* bp   = (const float*)d_in[10];
    float* out = (float*)d_out;

    float *qa, *ka, *wq, *wkv, *wp, *qp, *kvp, *attn;
    cudaGetSymbolAddress((void**)&qa,   g_qa);
    cudaGetSymbolAddress((void**)&ka,   g_ka);
    cudaGetSymbolAddress((void**)&wq,   g_wq);
    cudaGetSymbolAddress((void**)&wkv,  g_wkv);
    cudaGetSymbolAddress((void**)&wp,   g_wp);
    cudaGetSymbolAddress((void**)&qp,   g_qp);
    cudaGetSymbolAddress((void**)&kvp,  g_kvp);
    cudaGetSymbolAddress((void**)&attn, g_attn);

    // 0) pre-convert inputs/weights to tf32 + k-interleave
    conv_a_kernel<<<dim3(BL_ * D_ / 8 / 256, 2), 256>>>(q_in, qa, k_in, ka);
    conv_w_kernel<<<D_ * D_ / 4 / 256, 256>>>(Wq, wq, D_);
    conv_w_kernel<<<D_ * 2 * D_ / 4 / 256, 256>>>(Wkv, wkv, 2 * D_);
    conv_w_kernel<<<D_ * D_ / 4 / 256, 256>>>(Wp, wp, D_);

    cudaFuncSetAttribute(gemm_tf32_kernel, cudaFuncAttributeMaxDynamicSharedMemorySize, GSMEM);

    // 1) Q projection
    gemm_tf32_kernel<<<dim3(D_ / 128, BL_ / 128), 128, GSMEM>>>(qa, wq, bq, qp, BL_, D_, D_);
    // 2) KV projection
    gemm_tf32_kernel<<<dim3(2 * D_ / 128, BL_ / 128), 128, GSMEM>>>(ka, wkv, bkv, kvp, BL_, 2 * D_, D_);
    // 3) RoPE + split + V transpose
    rope_split_kernel<<<dim3(L_ / 64, BH_), 256>>>(rope);
    // 4) causal flash attention
    cudaFuncSetAttribute(flash_tc_kernel, cudaFuncAttributeMaxDynamicSharedMemorySize, FSMEM);
    flash_tc_kernel<<<dim3(BH_, L_ / 64), 128, FSMEM>>>();
    // 5) output projection
    gemm_tf32_kernel<<<dim3(D_ / 128, BL_ / 128), 128, GSMEM>>>(attn, wp, bp, out, BL_, D_, D_);
}

// round 16
// speedup vs baseline: 1.0585x; 1.0585x over previous
#include <cuda_runtime.h>
#include <math.h>
#include <stdint.h>

// Problem constants
#define B_   4
#define L_   2048
#define D_   1024
#define H_   16
#define HD_  64
#define BH_  (B_*H_)
#define BL_  (B_*L_)
#define SCALE_ 0.125f   // 1/sqrt(64)
#define LOG2E_ 1.4426950408889634f

// ---------------- scratch (device globals; no allocation allowed) ----------
__device__ float g_qa [BL_ * D_];          // q_in, tf32 + k-interleaved
__device__ float g_ka [BL_ * D_];          // k_in, tf32 + k-interleaved
__device__ float g_wq [D_ * D_];           // Wq,  tf32, rows k-interleaved
__device__ float g_wkv[D_ * 2 * D_];       // Wkv, tf32, rows k-interleaved
__device__ float g_wp [D_ * D_];           // Wp,  tf32, rows k-interleaved
__device__ float g_qp [BL_ * D_];          // q projection  [b*l][1024] fp32
__device__ float g_kvp[BL_ * 2 * D_];      // kv projection [b*l][2048] fp32
__device__ float g_q  [BH_ * L_ * HD_];    // [b,h,l,hd(interleaved)] tf32 bits
__device__ float g_k  [BH_ * L_ * HD_];    // [b,h,l,hd(interleaved)] tf32 bits
__device__ float g_vt [BH_ * HD_ * L_];    // [b,h,hd,l] transposed, tf32 bits
__device__ float g_attn[BL_ * D_];         // [b,l,h*hd] tf32 + k-interleaved

// ---------------- tf32 helpers ---------------------------------------------
__device__ __forceinline__ uint32_t f2tf(float f) {
    uint32_t r;
    asm("cvt.rna.tf32.f32 %0, %1;" : "=r"(r) : "f"(f));
    return r;
}
__device__ __forceinline__ float f2tf_f(float f) {
    return __uint_as_float(f2tf(f));
}
__device__ __forceinline__ float ex2(float x) {
    float r;
    asm("ex2.approx.f32 %0, %1;" : "=f"(r) : "f"(x));
    return r;
}

__device__ __forceinline__ void mma_tf32(float* d, const uint32_t* a, const uint32_t* b) {
    asm volatile(
        "mma.sync.aligned.m16n8k8.row.col.f32.tf32.tf32.f32 "
        "{%0,%1,%2,%3}, {%4,%5,%6,%7}, {%8,%9}, {%0,%1,%2,%3};"
        : "+f"(d[0]), "+f"(d[1]), "+f"(d[2]), "+f"(d[3])
        : "r"(a[0]), "r"(a[1]), "r"(a[2]), "r"(a[3]), "r"(b[0]), "r"(b[1]));
}

__device__ __forceinline__ void cp16(uint32_t smem_addr, const void* gptr) {
    asm volatile("cp.async.cg.shared.global [%0], [%1], 16;" :: "r"(smem_addr), "l"(gptr));
}
#define CP_COMMIT() asm volatile("cp.async.commit_group;")
#define CP_WAIT0()  asm volatile("cp.async.wait_group 0;")

// within-8 interleave: logical w -> phys ((w&3)<<1)|(w>>2)   (phys 2t <- logical t)
__device__ __forceinline__ int ilv(int j) {
    int w = j & 7;
    return (j & ~7) | (((w & 3) << 1) | (w >> 2));
}

// ---------------- pre-convert kernels --------------------------------------
// A matrices: fp32 -> tf32, interleave cols within groups of 8. y=0: q, y=1: k.
__global__ void __launch_bounds__(256) conv_a_kernel(
    const float* __restrict__ in0, float* __restrict__ out0,
    const float* __restrict__ in1, float* __restrict__ out1)
{
    const float* in  = blockIdx.y ? in1 : in0;
    float* out       = blockIdx.y ? out1 : out0;
    int idx = blockIdx.x * 256 + threadIdx.x;   // one per 8 cols
    const float4* ip = (const float4*)in + (size_t)idx * 2;
    float4 a = ip[0], b = ip[1];
    float4 o0 = make_float4(f2tf_f(a.x), f2tf_f(b.x), f2tf_f(a.y), f2tf_f(b.y));
    float4 o1 = make_float4(f2tf_f(a.z), f2tf_f(b.z), f2tf_f(a.w), f2tf_f(b.w));
    float4* op = (float4*)out + (size_t)idx * 2;
    op[0] = o0; op[1] = o1;
}

// W matrices merged: fp32 -> tf32, permute rows within groups of 8.
// segment 0: Wq (N=1024, 256K float4), 1: Wkv (N=2048, 512K), 2: Wp (N=1024, 256K)
__global__ void __launch_bounds__(256) conv_w_kernel(
    const float* __restrict__ wq_in,  float* __restrict__ wq_out,
    const float* __restrict__ wkv_in, float* __restrict__ wkv_out,
    const float* __restrict__ wp_in,  float* __restrict__ wp_out)
{
    int idx = blockIdx.x * 256 + threadIdx.x;
    const float* in; float* out; int N;
    if (idx < 262144)        { in = wq_in;  out = wq_out;  N = D_;     }
    else if (idx < 786432)   { in = wkv_in; out = wkv_out; N = 2 * D_; idx -= 262144; }
    else                     { in = wp_in;  out = wp_out;  N = D_;     idx -= 786432; }
    int n4 = N >> 2;
    int k = idx / n4;
    int c = (idx - k * n4) << 2;
    int kp = ilv(k);
    float4 v = *(const float4*)(in + (size_t)k * N + c);
    *(float4*)(out + (size_t)kp * N + c) =
        make_float4(f2tf_f(v.x), f2tf_f(v.y), f2tf_f(v.z), f2tf_f(v.w));
}

// ---------------- TF32 GEMM (R14 config: 256 thr, 2x4 warps, 64x32 tile) ---
#define GAS 40    // A smem row stride (words)
#define GBS 132   // B smem row stride (words)
#define GA_WORDS (128 * GAS)          // 5120
#define GB_WORDS (32 * GBS)           // 4224
#define GSTAGE   (GA_WORDS + GB_WORDS)
#define GSMEM    (2 * GSTAGE * 4)     // 74752 bytes

__device__ __forceinline__ void gemm_body(
    const float* __restrict__ A, const float* __restrict__ W,
    const float* __restrict__ bias, float* __restrict__ C,
    int N, int m0, int n0, uint32_t* smg)
{
    const int K = D_;
    const int tid = threadIdx.x;
    const int lane = tid & 31;
    const int wid = tid >> 5;
    const int g = lane >> 2, t = lane & 3;
    const int wm = (wid & 1) << 6;
    const int wn = (wid >> 1) << 5;

    float acc[4][4][4];
#pragma unroll
    for (int i = 0; i < 4; i++)
#pragma unroll
        for (int j = 0; j < 4; j++)
#pragma unroll
            for (int e = 0; e < 4; e++) acc[i][j][e] = 0.f;

    const int ar = tid >> 3;             // 0..31
    const int ac4 = (tid & 7) << 2;      // 0..28
    const int bk = tid >> 5;             // 0..7
    const int bc4 = (tid & 31) << 2;     // 0..124

    const uint32_t sbase = (uint32_t)__cvta_generic_to_shared(smg);
    const int NT = K >> 5;               // 32

    // prologue: tile 0 -> stage 0
    {
        uint32_t sa = sbase;
        uint32_t sb = sbase + GA_WORDS * 4;
#pragma unroll
        for (int u = 0; u < 4; u++) {
            int r = ar + (u << 5);
            cp16(sa + (uint32_t)(r * GAS + ac4) * 4, A + (size_t)(m0 + r) * K + ac4);
        }
#pragma unroll
        for (int u = 0; u < 4; u++) {
            int r = bk + (u << 3);
            cp16(sb + (uint32_t)(r * GBS + bc4) * 4, W + (size_t)r * N + n0 + bc4);
        }
        CP_COMMIT();
    }

    int cur = 0;
    for (int ti = 0; ti < NT; ti++) {
        CP_WAIT0();
        __syncthreads();

        if (ti + 1 < NT) {
            const int kt = (ti + 1) << 5;
            uint32_t sa = sbase + (cur ^ 1) * (GSTAGE * 4);
            uint32_t sb = sa + GA_WORDS * 4;
#pragma unroll
            for (int u = 0; u < 4; u++) {
                int r = ar + (u << 5);
                cp16(sa + (uint32_t)(r * GAS + ac4) * 4, A + (size_t)(m0 + r) * K + kt + ac4);
            }
#pragma unroll
            for (int u = 0; u < 4; u++) {
                int r = bk + (u << 3);
                cp16(sb + (uint32_t)(r * GBS + bc4) * 4, W + (size_t)(kt + r) * N + n0 + bc4);
            }
            CP_COMMIT();
        }

        const uint32_t* a_ = smg + cur * GSTAGE;
        const uint32_t* b_ = a_ + GA_WORDS;

#pragma unroll
        for (int kf = 0; kf < 4; kf++) {
            const int k0 = kf << 3;
            uint32_t af[4][4];
#pragma unroll
            for (int mf = 0; mf < 4; mf++) {
                const int r = wm + (mf << 4) + g;
                uint2 p0 = *(const uint2*)&a_[r * GAS + k0 + 2 * t];
                uint2 p1 = *(const uint2*)&a_[(r + 8) * GAS + k0 + 2 * t];
                af[mf][0] = p0.x; af[mf][1] = p1.x; af[mf][2] = p0.y; af[mf][3] = p1.y;
            }
            uint32_t bf[4][2];
#pragma unroll
            for (int nf = 0; nf < 4; nf++) {
                const int c = wn + (nf << 3) + g;
                bf[nf][0] = b_[(k0 + 2 * t) * GBS + c];
                bf[nf][1] = b_[(k0 + 2 * t + 1) * GBS + c];
            }
#pragma unroll
            for (int mf = 0; mf < 4; mf++)
#pragma unroll
                for (int nf = 0; nf < 4; nf++)
                    mma_tf32(acc[mf][nf], af[mf], bf[nf]);
        }
        cur ^= 1;
    }

    // epilogue
#pragma unroll
    for (int nf = 0; nf < 4; nf++) {
        const int col = n0 + wn + (nf << 3) + (t << 1);
        const float b0 = bias[col], b1 = bias[col + 1];
#pragma unroll
        for (int mf = 0; mf < 4; mf++) {
            const int row0 = m0 + wm + (mf << 4) + g;
            *(float2*)&C[(size_t)row0 * N + col] =
                make_float2(acc[mf][nf][0] + b0, acc[mf][nf][1] + b1);
            *(float2*)&C[(size_t)(row0 + 8) * N + col] =
                make_float2(acc[mf][nf][2] + b0, acc[mf][nf][3] + b1);
        }
    }
}

// merged Q + KV projection: blocks [0,512) -> Q, [512,1536) -> KV
__global__ void __launch_bounds__(256, 2) gemm_qkv_kernel(
    const float* __restrict__ bq, const float* __restrict__ bkv)
{
    extern __shared__ uint32_t smg[];
    int bid = blockIdx.x;
    if (bid < 512) {
        int m0 = (bid >> 3) << 7;
        int n0 = (bid & 7) << 7;
        gemm_body(g_qa, g_wq, bq, g_qp, D_, m0, n0, smg);
    } else {
        bid -= 512;
        int m0 = (bid >> 4) << 7;
        int n0 = (bid & 15) << 7;
        gemm_body(g_ka, g_wkv, bkv, g_kvp, 2 * D_, m0, n0, smg);
    }
}

// out projection
__global__ void __launch_bounds__(256, 2) gemm_out_kernel(
    const float* __restrict__ bp, float* __restrict__ out)
{
    extern __shared__ uint32_t smg[];
    int bid = blockIdx.x;
    int m0 = (bid >> 3) << 7;
    int n0 = (bid & 7) << 7;
    gemm_body(g_attn, g_wp, bp, out, D_, m0, n0, smg);
}

// ---------------- RoPE + head split + V transpose (all outputs tf32) -------
__global__ void __launch_bounds__(256) rope_split_kernel(const float* __restrict__ rope)
{
    __shared__ float sv[64][65];

    const int tid = threadIdx.x;
    const int l0 = blockIdx.x << 6;
    const int bh = blockIdx.y;
    const int b = bh >> 4, h = bh & 15;

    const int p = tid & 31;
    const int lr = (tid >> 5) << 3;

    const int j0 = ilv(2 * p);
    const int j1 = ilv(2 * p + 1);

#pragma unroll
    for (int u = 0; u < 8; u++) {
        const int l = lr + u;
        float2 rp = ((const float2*)rope)[(l0 + l) * 32 + p];
        const float sn = rp.x, cs = rp.y;

        const size_t rowq = (size_t)(b * L_ + l0 + l);
        float2 q = ((const float2*)g_qp)[rowq * 512 + h * 32 + p];
        const size_t kvb = rowq * 1024;
        float2 k = ((const float2*)g_kvp)[kvb + h * 32 + p];
        float2 v = ((const float2*)g_kvp)[kvb + 512 + h * 32 + p];

        float qe = q.x * cs - q.y * sn, qo = q.x * sn + q.y * cs;
        float ke = k.x * cs - k.y * sn, ko = k.x * sn + k.y * cs;

        const size_t ob = (size_t)(bh * L_ + l0 + l) * 64;
        g_q[ob + j0] = f2tf_f(qe);
        g_q[ob + j1] = f2tf_f(qo);
        g_k[ob + j0] = f2tf_f(ke);
        g_k[ob + j1] = f2tf_f(ko);

        sv[l][2 * p]     = v.x;
        sv[l][2 * p + 1] = v.y;
    }
    __syncthreads();

    const int hd = tid >> 2;
    const int c0 = (tid & 3) << 4;
    float* dst = g_vt + ((size_t)bh * 64 + hd) * L_ + l0 + c0;
#pragma unroll
    for (int j4 = 0; j4 < 4; j4++) {
        float4 o;
        o.x = f2tf_f(sv[c0 + j4 * 4 + 0][hd]);
        o.y = f2tf_f(sv[c0 + j4 * 4 + 1][hd]);
        o.z = f2tf_f(sv[c0 + j4 * 4 + 2][hd]);
        o.w = f2tf_f(sv[c0 + j4 * 4 + 3][hd]);
        *(float4*)(dst + j4 * 4) = o;
    }
}

// ---------------- causal flash attention (tf32 mma, cp.async pipelined) ----
#define FS 72
#define FTILE (64 * FS)
#define FSMEM (4 * FTILE * 4)

__global__ void __launch_bounds__(128) flash_tc_kernel()
{
    extern __shared__ float smf[];
    float* bufK[2] = { smf,             smf + 2 * FTILE };
    float* bufV[2] = { smf + FTILE,     smf + 3 * FTILE };

    const int tid = threadIdx.x;
    const int lane = tid & 31;
    const int wid = tid >> 5;
    const int g = lane >> 2, t = lane & 3;
    const int bh = blockIdx.x;
    const int qb = 31 - blockIdx.y;     // heavy blocks first
    const int q0 = qb * 64;
    const int b = bh >> 4, h = bh & 15;
    const int mrow = wid << 4;

    const float* Qg = g_q + ((size_t)bh * L_ + q0) * HD_;
    const float* Kg = g_k + (size_t)bh * L_ * HD_;
    const float* Vt = g_vt + (size_t)bh * HD_ * L_;

    const int cr = tid >> 4;
    const int cc4 = (tid & 15) << 2;

    {
        uint32_t skb = (uint32_t)__cvta_generic_to_shared(bufK[0]);
        uint32_t svb = (uint32_t)__cvta_generic_to_shared(bufV[0]);
#pragma unroll
        for (int u = 0; u < 8; u++) {
            int r = cr + (u << 3);
            cp16(skb + (uint32_t)(r * FS + cc4) * 4, Kg + (size_t)r * 64 + cc4);
            cp16(svb + (uint32_t)(r * FS + cc4) * 4, Vt + (size_t)r * L_ + cc4);
        }
        CP_COMMIT();
    }

    // stage Q into buf1 K region
#pragma unroll
    for (int u = 0; u < 8; u++) {
        int idx = tid + (u << 7);
        int r = idx >> 4;
        int c4 = (idx & 15) << 2;
        *(float4*)&bufK[1][r * FS + c4] = *(const float4*)(Qg + (size_t)r * 64 + c4);
    }
    __syncthreads();

    uint32_t qf[8][4];
#pragma unroll
    for (int kf = 0; kf < 8; kf++) {
        uint2 p0 = *(const uint2*)&bufK[1][(mrow + g) * FS + (kf << 3) + 2 * t];
        uint2 p1 = *(const uint2*)&bufK[1][(mrow + g + 8) * FS + (kf << 3) + 2 * t];
        qf[kf][0] = p0.x; qf[kf][1] = p1.x; qf[kf][2] = p0.y; qf[kf][3] = p1.y;
    }

    float Of[8][4];
    float m_i[2] = {-INFINITY, -INFINITY};
    float l_i[2] = {0.f, 0.f};
#pragma unroll
    for (int nf = 0; nf < 8; nf++)
#pragma unroll
        for (int e = 0; e < 4; e++) Of[nf][e] = 0.f;

    const float SC2 = SCALE_ * LOG2E_;
    int cur = 0;

    for (int kb = 0; kb <= qb; kb++) {
        CP_WAIT0();
        __syncthreads();

        if (kb < qb) {
            const int nn = (kb + 1) * 64;
            uint32_t skb = (uint32_t)__cvta_generic_to_shared(bufK[cur ^ 1]);
            uint32_t svb = (uint32_t)__cvta_generic_to_shared(bufV[cur ^ 1]);
#pragma unroll
            for (int u = 0; u < 8; u++) {
                int r = cr + (u << 3);
                cp16(skb + (uint32_t)(r * FS + cc4) * 4, Kg + (size_t)(nn + r) * 64 + cc4);
                cp16(svb + (uint32_t)(r * FS + cc4) * 4, Vt + (size_t)r * L_ + nn + cc4);
            }
            CP_COMMIT();
        }

        const uint32_t* sK = (const uint32_t*)bufK[cur];
        const uint32_t* sV = (const uint32_t*)bufV[cur];
        const int n0 = kb * 64;

        // S = Q K^T  (kf outer -> 8 independent accumulator chains)
        float Sf[8][4];
#pragma unroll
        for (int nf = 0; nf < 8; nf++)
#pragma unroll
            for (int e = 0; e < 4; e++) Sf[nf][e] = 0.f;

#pragma unroll
        for (int kf = 0; kf < 8; kf++) {
            const uint32_t* kbase = sK + (kf << 3) + 2 * t;
#pragma unroll
            for (int nf = 0; nf < 8; nf++) {
                uint2 bv = *(const uint2*)(kbase + ((nf << 3) + g) * FS);
                uint32_t bfr[2] = { bv.x, bv.y };
                mma_tf32(Sf[nf], qf[kf], bfr);
            }
        }

        const int row0 = q0 + mrow + g;
        const int row1 = row0 + 8;
        const bool diag = (kb == qb);
#pragma unroll
        for (int nf = 0; nf < 8; nf++) {
            Sf[nf][0] *= SC2; Sf[nf][1] *= SC2;
            Sf[nf][2] *= SC2; Sf[nf][3] *= SC2;
            if (diag) {
                const int c0 = n0 + (nf << 3) + 2 * t;
                if (c0 > row0)     Sf[nf][0] = -1e9f;
                if (c0 + 1 > row0) Sf[nf][1] = -1e9f;
                if (c0 > row1)     Sf[nf][2] = -1e9f;
                if (c0 + 1 > row1) Sf[nf][3] = -1e9f;
            }
        }

        float rm0 = -INFINITY, rm1 = -INFINITY;
#pragma unroll
        for (int nf = 0; nf < 8; nf++) {
            rm0 = fmaxf(rm0, fmaxf(Sf[nf][0], Sf[nf][1]));
            rm1 = fmaxf(rm1, fmaxf(Sf[nf][2], Sf[nf][3]));
        }
        rm0 = fmaxf(rm0, __shfl_xor_sync(0xffffffffu, rm0, 1));
        rm0 = fmaxf(rm0, __shfl_xor_sync(0xffffffffu, rm0, 2));
        rm1 = fmaxf(rm1, __shfl_xor_sync(0xffffffffu, rm1, 1));
        rm1 = fmaxf(rm1, __shfl_xor_sync(0xffffffffu, rm1, 2));

        const float mn0 = fmaxf(m_i[0], rm0);
        const float mn1 = fmaxf(m_i[1], rm1);
        const float corr0 = ex2(m_i[0] - mn0);
        const float corr1 = ex2(m_i[1] - mn1);
        m_i[0] = mn0; m_i[1] = mn1;

        uint32_t pa[8][4];
        float ps0 = 0.f, ps1 = 0.f;
#pragma unroll
        for (int nf = 0; nf < 8; nf++) {
            float p0 = ex2(Sf[nf][0] - mn0);
            float p1 = ex2(Sf[nf][1] - mn0);
            float p2 = ex2(Sf[nf][2] - mn1);
            float p3 = ex2(Sf[nf][3] - mn1);
            ps0 += p0 + p1;
            ps1 += p2 + p3;
            pa[nf][0] = f2tf(p0); pa[nf][1] = f2tf(p2);
            pa[nf][2] = f2tf(p1); pa[nf][3] = f2tf(p3);
        }
        ps0 += __shfl_xor_sync(0xffffffffu, ps0, 1);
        ps0 += __shfl_xor_sync(0xffffffffu, ps0, 2);
        ps1 += __shfl_xor_sync(0xffffffffu, ps1, 1);
        ps1 += __shfl_xor_sync(0xffffffffu, ps1, 2);
        l_i[0] = l_i[0] * corr0 + ps0;
        l_i[1] = l_i[1] * corr1 + ps1;

#pragma unroll
        for (int nf = 0; nf < 8; nf++) {
            Of[nf][0] *= corr0; Of[nf][1] *= corr0;
            Of[nf][2] *= corr1; Of[nf][3] *= corr1;
        }

        // O += P @ V  (pc outer -> independent chains across onf)
#pragma unroll
        for (int pc = 0; pc < 8; pc++) {
#pragma unroll
            for (int onf = 0; onf < 8; onf++) {
                uint2 vv = *(const uint2*)(sV + ((onf << 3) + g) * FS + (pc << 3) + 2 * t);
                uint32_t bfr[2] = { vv.x, vv.y };
                mma_tf32(Of[onf], pa[pc], bfr);
            }
        }
        cur ^= 1;
    }

    // normalize + write g_attn as tf32 + k-interleaved (for out-proj GEMM)
    const float inv0 = 1.f / l_i[0];
    const float inv1 = 1.f / l_i[1];
    const int row0 = q0 + mrow + g;
    const int row1 = row0 + 8;
    const int pc0 = ((t & 1) << 2) | (t >> 1);   // phys(2t): {0,4,1,5}
#pragma unroll
    for (int nf = 0; nf < 8; nf++) {
        const int basec = h * HD_ + (nf << 3);
        g_attn[(size_t)(b * L_ + row0) * D_ + basec + pc0]     = f2tf_f(Of[nf][0] * inv0);
        g_attn[(size_t)(b * L_ + row0) * D_ + basec + pc0 + 2] = f2tf_f(Of[nf][1] * inv0);
        g_attn[(size_t)(b * L_ + row1) * D_ + basec + pc0]     = f2tf_f(Of[nf][2] * inv1);
        g_attn[(size_t)(b * L_ + row1) * D_ + basec + pc0 + 2] = f2tf_f(Of[nf][3] * inv1);
    }
}

// ---------------- launch ----------------------------------------------------
extern "C" void kernel_launch(void* const* d_in, const int* in_sizes, int n_in,
                              void* d_out, int out_size)
{
    const float* q_in = (const float*)d_in[0];
    const float* k_in = (const float*)d_in[1];
    // d_in[2] = v_in (unused by reference), d_in[3] = mask (tril, hardcoded causal)
    const float* rope = (const float*)d_in[4];
    const float* Wq   = (const float*)d_in[5];
    const float* bq   = (const float*)d_in[6];
    const float* Wkv  = (const float*)d_in[7];
    const float* bkv  = (const float*)d_in[8];
    const float* Wp   = (const float*)d_in[9];
    const float* bp   = (const float*)d_in[10];
    float* out = (float*)d_out;

    float *qa, *ka, *wq, *wkv, *wp;
    cudaGetSymbolAddress((void**)&qa,   g_qa);
    cudaGetSymbolAddress((void**)&ka,   g_ka);
    cudaGetSymbolAddress((void**)&wq,   g_wq);
    cudaGetSymbolAddress((void**)&wkv,  g_wkv);
    cudaGetSymbolAddress((void**)&wp,   g_wp);

    // 0) pre-convert inputs/weights to tf32 + k-interleave
    conv_a_kernel<<<dim3(BL_ * D_ / 8 / 256, 2), 256>>>(q_in, qa, k_in, ka);
    conv_w_kernel<<<(D_ * D_ * 4) / 4 / 256, 256>>>(Wq, wq, Wkv, wkv, Wp, wp);

    cudaFuncSetAttribute(gemm_qkv_kernel, cudaFuncAttributeMaxDynamicSharedMemorySize, GSMEM);
    cudaFuncSetAttribute(gemm_out_kernel, cudaFuncAttributeMaxDynamicSharedMemorySize, GSMEM);

    // 1+2) Q and KV projections, single launch
    gemm_qkv_kernel<<<1536, 256, GSMEM>>>(bq, bkv);
    // 3) RoPE + split + V transpose
    rope_split_kernel<<<dim3(L_ / 64, BH_), 256>>>(rope);
    // 4) causal flash attention
    cudaFuncSetAttribute(flash_tc_kernel, cudaFuncAttributeMaxDynamicSharedMemorySize, FSMEM);
    flash_tc_kernel<<<dim3(BH_, L_ / 64), 128, FSMEM>>>();
    // 5) output projection
    gemm_out_kernel<<<512, 256, GSMEM>>>(bp, out);
}

// round 17
// speedup vs baseline: 1.0718x; 1.0126x over previous
#include <cuda_runtime.h>
#include <math.h>
#include <stdint.h>

// Problem constants
#define B_   4
#define L_   2048
#define D_   1024
#define H_   16
#define HD_  64
#define BH_  (B_*H_)
#define BL_  (B_*L_)
#define SCALE_ 0.125f   // 1/sqrt(64)
#define LOG2E_ 1.4426950408889634f

// ---------------- scratch (device globals; no allocation allowed) ----------
__device__ float g_qa [BL_ * D_];          // q_in, tf32 + k-interleaved
__device__ float g_ka [BL_ * D_];          // k_in, tf32 + k-interleaved
__device__ float g_wq [D_ * D_];           // Wq,  tf32, rows k-interleaved
__device__ float g_wkv[D_ * 2 * D_];       // Wkv, tf32, rows k-interleaved
__device__ float g_wp [D_ * D_];           // Wp,  tf32, rows k-interleaved
__device__ float g_q  [BH_ * L_ * HD_];    // [b,h,l,hd(interleaved)] tf32 bits
__device__ float g_k  [BH_ * L_ * HD_];    // [b,h,l,hd(interleaved)] tf32 bits
__device__ float g_vt [BH_ * HD_ * L_];    // [b,h,hd,l] transposed, tf32 bits
__device__ float g_attn[BL_ * D_];         // [b,l,h*hd] tf32 + k-interleaved

// ---------------- tf32 helpers ---------------------------------------------
__device__ __forceinline__ uint32_t f2tf(float f) {
    uint32_t r;
    asm("cvt.rna.tf32.f32 %0, %1;" : "=r"(r) : "f"(f));
    return r;
}
__device__ __forceinline__ float f2tf_f(float f) {
    return __uint_as_float(f2tf(f));
}
__device__ __forceinline__ float ex2(float x) {
    float r;
    asm("ex2.approx.f32 %0, %1;" : "=f"(r) : "f"(x));
    return r;
}

__device__ __forceinline__ void mma_tf32(float* d, const uint32_t* a, const uint32_t* b) {
    asm volatile(
        "mma.sync.aligned.m16n8k8.row.col.f32.tf32.tf32.f32 "
        "{%0,%1,%2,%3}, {%4,%5,%6,%7}, {%8,%9}, {%0,%1,%2,%3};"
        : "+f"(d[0]), "+f"(d[1]), "+f"(d[2]), "+f"(d[3])
        : "r"(a[0]), "r"(a[1]), "r"(a[2]), "r"(a[3]), "r"(b[0]), "r"(b[1]));
}

__device__ __forceinline__ void cp16(uint32_t smem_addr, const void* gptr) {
    asm volatile("cp.async.cg.shared.global [%0], [%1], 16;" :: "r"(smem_addr), "l"(gptr));
}
#define CP_COMMIT() asm volatile("cp.async.commit_group;")
#define CP_WAIT0()  asm volatile("cp.async.wait_group 0;")

// within-8 interleave: logical w -> phys ((w&3)<<1)|(w>>2)   (phys 2t <- logical t)
__device__ __forceinline__ int ilv(int j) {
    int w = j & 7;
    return (j & ~7) | (((w & 3) << 1) | (w >> 2));
}

// ---------------- pre-convert kernels --------------------------------------
__global__ void __launch_bounds__(256) conv_a_kernel(
    const float* __restrict__ in0, float* __restrict__ out0,
    const float* __restrict__ in1, float* __restrict__ out1)
{
    const float* in  = blockIdx.y ? in1 : in0;
    float* out       = blockIdx.y ? out1 : out0;
    int idx = blockIdx.x * 256 + threadIdx.x;   // one per 8 cols
    const float4* ip = (const float4*)in + (size_t)idx * 2;
    float4 a = ip[0], b = ip[1];
    float4 o0 = make_float4(f2tf_f(a.x), f2tf_f(b.x), f2tf_f(a.y), f2tf_f(b.y));
    float4 o1 = make_float4(f2tf_f(a.z), f2tf_f(b.z), f2tf_f(a.w), f2tf_f(b.w));
    float4* op = (float4*)out + (size_t)idx * 2;
    op[0] = o0; op[1] = o1;
}

__global__ void __launch_bounds__(256) conv_w_kernel(
    const float* __restrict__ wq_in,  float* __restrict__ wq_out,
    const float* __restrict__ wkv_in, float* __restrict__ wkv_out,
    const float* __restrict__ wp_in,  float* __restrict__ wp_out)
{
    int idx = blockIdx.x * 256 + threadIdx.x;
    const float* in; float* out; int N;
    if (idx < 262144)        { in = wq_in;  out = wq_out;  N = D_;     }
    else if (idx < 786432)   { in = wkv_in; out = wkv_out; N = 2 * D_; idx -= 262144; }
    else                     { in = wp_in;  out = wp_out;  N = D_;     idx -= 786432; }
    int n4 = N >> 2;
    int k = idx / n4;
    int c = (idx - k * n4) << 2;
    int kp = ilv(k);
    float4 v = *(const float4*)(in + (size_t)k * N + c);
    *(float4*)(out + (size_t)kp * N + c) =
        make_float4(f2tf_f(v.x), f2tf_f(v.y), f2tf_f(v.z), f2tf_f(v.w));
}

// ---------------- TF32 GEMM core (256 thr, 2x4 warps, 64x32 warp tile) -----
#define GAS 40    // A smem row stride (words)
#define GBS 132   // B smem row stride (words)
#define GA_WORDS (128 * GAS)          // 5120
#define GB_WORDS (32 * GBS)           // 4224
#define GSTAGE   (GA_WORDS + GB_WORDS)
#define GSMEM    (2 * GSTAGE * 4)     // 74752 bytes
#define TS 132    // epilogue staging tile stride (floats)

// mainloop: fills acc[4][4][4]. No epilogue.
__device__ __forceinline__ void gemm_core(
    const float* __restrict__ A, const float* __restrict__ W,
    int N, int m0, int n0, uint32_t* smg, float acc[4][4][4])
{
    const int K = D_;
    const int tid = threadIdx.x;
    const int lane = tid & 31;
    const int wid = tid >> 5;
    const int g = lane >> 2, t = lane & 3;
    const int wm = (wid & 1) << 6;
    const int wn = (wid >> 1) << 5;

#pragma unroll
    for (int i = 0; i < 4; i++)
#pragma unroll
        for (int j = 0; j < 4; j++)
#pragma unroll
            for (int e = 0; e < 4; e++) acc[i][j][e] = 0.f;

    const int ar = tid >> 3;
    const int ac4 = (tid & 7) << 2;
    const int bk = tid >> 5;
    const int bc4 = (tid & 31) << 2;

    const uint32_t sbase = (uint32_t)__cvta_generic_to_shared(smg);
    const int NT = K >> 5;

    {
        uint32_t sa = sbase;
        uint32_t sb = sbase + GA_WORDS * 4;
#pragma unroll
        for (int u = 0; u < 4; u++) {
            int r = ar + (u << 5);
            cp16(sa + (uint32_t)(r * GAS + ac4) * 4, A + (size_t)(m0 + r) * K + ac4);
        }
#pragma unroll
        for (int u = 0; u < 4; u++) {
            int r = bk + (u << 3);
            cp16(sb + (uint32_t)(r * GBS + bc4) * 4, W + (size_t)r * N + n0 + bc4);
        }
        CP_COMMIT();
    }

    int cur = 0;
    for (int ti = 0; ti < NT; ti++) {
        CP_WAIT0();
        __syncthreads();

        if (ti + 1 < NT) {
            const int kt = (ti + 1) << 5;
            uint32_t sa = sbase + (cur ^ 1) * (GSTAGE * 4);
            uint32_t sb = sa + GA_WORDS * 4;
#pragma unroll
            for (int u = 0; u < 4; u++) {
                int r = ar + (u << 5);
                cp16(sa + (uint32_t)(r * GAS + ac4) * 4, A + (size_t)(m0 + r) * K + kt + ac4);
            }
#pragma unroll
            for (int u = 0; u < 4; u++) {
                int r = bk + (u << 3);
                cp16(sb + (uint32_t)(r * GBS + bc4) * 4, W + (size_t)(kt + r) * N + n0 + bc4);
            }
            CP_COMMIT();
        }

        const uint32_t* a_ = smg + cur * GSTAGE;
        const uint32_t* b_ = a_ + GA_WORDS;

#pragma unroll
        for (int kf = 0; kf < 4; kf++) {
            const int k0 = kf << 3;
            uint32_t af[4][4];
#pragma unroll
            for (int mf = 0; mf < 4; mf++) {
                const int r = wm + (mf << 4) + g;
                uint2 p0 = *(const uint2*)&a_[r * GAS + k0 + 2 * t];
                uint2 p1 = *(const uint2*)&a_[(r + 8) * GAS + k0 + 2 * t];
                af[mf][0] = p0.x; af[mf][1] = p1.x; af[mf][2] = p0.y; af[mf][3] = p1.y;
            }
            uint32_t bf[4][2];
#pragma unroll
            for (int nf = 0; nf < 4; nf++) {
                const int c = wn + (nf << 3) + g;
                bf[nf][0] = b_[(k0 + 2 * t) * GBS + c];
                bf[nf][1] = b_[(k0 + 2 * t + 1) * GBS + c];
            }
#pragma unroll
            for (int mf = 0; mf < 4; mf++)
#pragma unroll
                for (int nf = 0; nf < 4; nf++)
                    mma_tf32(acc[mf][nf], af[mf], bf[nf]);
        }
        cur ^= 1;
    }
}

// stage acc+bias into smem tile T[128][TS]
__device__ __forceinline__ void stage_acc(
    float* T, float acc[4][4][4], const float* __restrict__ bias, int n0)
{
    const int tid = threadIdx.x;
    const int lane = tid & 31;
    const int wid = tid >> 5;
    const int g = lane >> 2, t = lane & 3;
    const int wm = (wid & 1) << 6;
    const int wn = (wid >> 1) << 5;
#pragma unroll
    for (int nf = 0; nf < 4; nf++) {
        const int lc = wn + (nf << 3) + (t << 1);
        const float b0 = bias[n0 + lc], b1 = bias[n0 + lc + 1];
#pragma unroll
        for (int mf = 0; mf < 4; mf++) {
            const int lr = wm + (mf << 4) + g;
            *(float2*)&T[lr * TS + lc] =
                make_float2(acc[mf][nf][0] + b0, acc[mf][nf][1] + b1);
            *(float2*)&T[(lr + 8) * TS + lc] =
                make_float2(acc[mf][nf][2] + b0, acc[mf][nf][3] + b1);
        }
    }
}

// merged Q + KV projection with fused RoPE / split / V-transpose epilogue.
// blocks [0,512) -> Q proj; [512,1536) -> KV proj.
__global__ void __launch_bounds__(256, 2) gemm_qkv_kernel(
    const float* __restrict__ bq, const float* __restrict__ bkv,
    const float* __restrict__ rope)
{
    extern __shared__ uint32_t smg[];
    float acc[4][4][4];

    int bid = blockIdx.x;
    int m0, n0, mode;          // mode: 0=Q rope, 1=K rope, 2=V transpose
    const float* bias;
    if (bid < 512) {
        m0 = (bid >> 3) << 7;
        n0 = (bid & 7) << 7;
        bias = bq;
        mode = 0;
        gemm_core(g_qa, g_wq, D_, m0, n0, smg, acc);
    } else {
        bid -= 512;
        m0 = (bid >> 4) << 7;
        n0 = (bid & 15) << 7;
        bias = bkv;
        mode = (n0 < 1024) ? 1 : 2;
        gemm_core(g_ka, g_wkv, 2 * D_, m0, n0, smg, acc);
    }

    __syncthreads();               // all warps done reading pipeline smem
    float* T = (float*)smg;        // reuse as staging tile [128][TS]
    stage_acc(T, acc, bias, n0);
    __syncthreads();

    const int tid = threadIdx.x;
    const int b = m0 >> 11;        // block spans one batch (128 | 2048)
    const int l0 = m0 & (L_ - 1);

    if (mode == 2) {
        // V: transpose to g_vt[bh][hd][l], tf32
        const int col = tid >> 1;          // 0..127
        const int half = tid & 1;          // l half
        const int vc = (n0 - 1024) + col;
        const int h = vc >> 6, hd = vc & 63;
        float* dst = g_vt + ((size_t)((b * H_ + h) * HD_ + hd)) * L_ + l0 + half * 64;
#pragma unroll
        for (int j4 = 0; j4 < 16; j4++) {
            const int r = half * 64 + (j4 << 2);
            float4 o;
            o.x = f2tf_f(T[(r + 0) * TS + col]);
            o.y = f2tf_f(T[(r + 1) * TS + col]);
            o.z = f2tf_f(T[(r + 2) * TS + col]);
            o.w = f2tf_f(T[(r + 3) * TS + col]);
            *(float4*)(dst + (j4 << 2)) = o;
        }
    } else {
        // Q or K: rope rotate pairs + hd-interleave, write tf32
        float* dstbase = (mode == 0) ? g_q : g_k;
#pragma unroll
        for (int u = 0; u < 8; u++) {
            const int gi = tid + (u << 8);
            const int r = gi >> 4;                 // 0..127
            const int c8 = (gi & 15) << 3;         // 0..120
            const int l = l0 + r;
            const int col = n0 + c8;
            const int h = col >> 6;
            const int hb = col & 63;               // 8-aligned hd group base

            float v8[8];
#pragma unroll
            for (int j = 0; j < 8; j++) v8[j] = T[r * TS + c8 + j];

            float4 rp0 = *(const float4*)(rope + (size_t)l * HD_ + hb);
            float4 rp1 = *(const float4*)(rope + (size_t)l * HD_ + hb + 4);
            const float sn[4] = { rp0.x, rp0.z, rp1.x, rp1.z };
            const float cs[4] = { rp0.y, rp0.w, rp1.y, rp1.w };

            float re[4], ro[4];
#pragma unroll
            for (int j = 0; j < 4; j++) {
                const float e = v8[2 * j], o = v8[2 * j + 1];
                re[j] = e * cs[j] - o * sn[j];
                ro[j] = e * sn[j] + o * cs[j];
            }
            // phys order within 8-group: {re0, re2, ro0, ro2, re1, re3, ro1, ro3}
            float4 o0 = make_float4(f2tf_f(re[0]), f2tf_f(re[2]), f2tf_f(ro[0]), f2tf_f(ro[2]));
            float4 o1 = make_float4(f2tf_f(re[1]), f2tf_f(re[3]), f2tf_f(ro[1]), f2tf_f(ro[3]));
            float* dst = dstbase + ((size_t)((b * H_ + h) * L_ + l)) * HD_ + hb;
            *(float4*)(dst)     = o0;
            *(float4*)(dst + 4) = o1;
        }
    }
}

// out projection: plain epilogue
__global__ void __launch_bounds__(256, 2) gemm_out_kernel(
    const float* __restrict__ bp, float* __restrict__ out)
{
    extern __shared__ uint32_t smg[];
    float acc[4][4][4];
    int bid = blockIdx.x;
    int m0 = (bid >> 3) << 7;
    int n0 = (bid & 7) << 7;
    gemm_core(g_attn, g_wp, D_, m0, n0, smg, acc);

    const int tid = threadIdx.x;
    const int lane = tid & 31;
    const int wid = tid >> 5;
    const int g = lane >> 2, t = lane & 3;
    const int wm = (wid & 1) << 6;
    const int wn = (wid >> 1) << 5;
#pragma unroll
    for (int nf = 0; nf < 4; nf++) {
        const int col = n0 + wn + (nf << 3) + (t << 1);
        const float b0 = bp[col], b1 = bp[col + 1];
#pragma unroll
        for (int mf = 0; mf < 4; mf++) {
            const int row0 = m0 + wm + (mf << 4) + g;
            *(float2*)&out[(size_t)row0 * D_ + col] =
                make_float2(acc[mf][nf][0] + b0, acc[mf][nf][1] + b1);
            *(float2*)&out[(size_t)(row0 + 8) * D_ + col] =
                make_float2(acc[mf][nf][2] + b0, acc[mf][nf][3] + b1);
        }
    }
}

// ---------------- causal flash attention (tf32 mma, cp.async pipelined) ----
#define FS 72
#define FTILE (64 * FS)
#define FSMEM (4 * FTILE * 4)

__global__ void __launch_bounds__(128) flash_tc_kernel()
{
    extern __shared__ float smf[];
    float* bufK[2] = { smf,             smf + 2 * FTILE };
    float* bufV[2] = { smf + FTILE,     smf + 3 * FTILE };

    const int tid = threadIdx.x;
    const int lane = tid & 31;
    const int wid = tid >> 5;
    const int g = lane >> 2, t = lane & 3;
    const int bh = blockIdx.x;
    const int qb = 31 - blockIdx.y;     // heavy blocks first
    const int q0 = qb * 64;
    const int b = bh >> 4, h = bh & 15;
    const int mrow = wid << 4;

    const float* Qg = g_q + ((size_t)bh * L_ + q0) * HD_;
    const float* Kg = g_k + (size_t)bh * L_ * HD_;
    const float* Vt = g_vt + (size_t)bh * HD_ * L_;

    const int cr = tid >> 4;
    const int cc4 = (tid & 15) << 2;

    {
        uint32_t skb = (uint32_t)__cvta_generic_to_shared(bufK[0]);
        uint32_t svb = (uint32_t)__cvta_generic_to_shared(bufV[0]);
#pragma unroll
        for (int u = 0; u < 8; u++) {
            int r = cr + (u << 3);
            cp16(skb + (uint32_t)(r * FS + cc4) * 4, Kg + (size_t)r * 64 + cc4);
            cp16(svb + (uint32_t)(r * FS + cc4) * 4, Vt + (size_t)r * L_ + cc4);
        }
        CP_COMMIT();
    }

    // stage Q into buf1 K region
#pragma unroll
    for (int u = 0; u < 8; u++) {
        int idx = tid + (u << 7);
        int r = idx >> 4;
        int c4 = (idx & 15) << 2;
        *(float4*)&bufK[1][r * FS + c4] = *(const float4*)(Qg + (size_t)r * 64 + c4);
    }
    __syncthreads();

    uint32_t qf[8][4];
#pragma unroll
    for (int kf = 0; kf < 8; kf++) {
        uint2 p0 = *(const uint2*)&bufK[1][(mrow + g) * FS + (kf << 3) + 2 * t];
        uint2 p1 = *(const uint2*)&bufK[1][(mrow + g + 8) * FS + (kf << 3) + 2 * t];
        qf[kf][0] = p0.x; qf[kf][1] = p1.x; qf[kf][2] = p0.y; qf[kf][3] = p1.y;
    }

    float Of[8][4];
    float m_i[2] = {-INFINITY, -INFINITY};
    float l_i[2] = {0.f, 0.f};
#pragma unroll
    for (int nf = 0; nf < 8; nf++)
#pragma unroll
        for (int e = 0; e < 4; e++) Of[nf][e] = 0.f;

    const float SC2 = SCALE_ * LOG2E_;
    int cur = 0;

    for (int kb = 0; kb <= qb; kb++) {
        CP_WAIT0();
        __syncthreads();

        if (kb < qb) {
            const int nn = (kb + 1) * 64;
            uint32_t skb = (uint32_t)__cvta_generic_to_shared(bufK[cur ^ 1]);
            uint32_t svb = (uint32_t)__cvta_generic_to_shared(bufV[cur ^ 1]);
#pragma unroll
            for (int u = 0; u < 8; u++) {
                int r = cr + (u << 3);
                cp16(skb + (uint32_t)(r * FS + cc4) * 4, Kg + (size_t)(nn + r) * 64 + cc4);
                cp16(svb + (uint32_t)(r * FS + cc4) * 4, Vt + (size_t)r * L_ + nn + cc4);
            }
            CP_COMMIT();
        }

        const uint32_t* sK = (const uint32_t*)bufK[cur];
        const uint32_t* sV = (const uint32_t*)bufV[cur];
        const int n0 = kb * 64;

        float Sf[8][4];
#pragma unroll
        for (int nf = 0; nf < 8; nf++)
#pragma unroll
            for (int e = 0; e < 4; e++) Sf[nf][e] = 0.f;

#pragma unroll
        for (int kf = 0; kf < 8; kf++) {
            const uint32_t* kbase = sK + (kf << 3) + 2 * t;
#pragma unroll
            for (int nf = 0; nf < 8; nf++) {
                uint2 bv = *(const uint2*)(kbase + ((nf << 3) + g) * FS);
                uint32_t bfr[2] = { bv.x, bv.y };
                mma_tf32(Sf[nf], qf[kf], bfr);
            }
        }

        const int row0 = q0 + mrow + g;
        const int row1 = row0 + 8;
        const bool diag = (kb == qb);
#pragma unroll
        for (int nf = 0; nf < 8; nf++) {
            Sf[nf][0] *= SC2; Sf[nf][1] *= SC2;
            Sf[nf][2] *= SC2; Sf[nf][3] *= SC2;
            if (diag) {
                const int c0 = n0 + (nf << 3) + 2 * t;
                if (c0 > row0)     Sf[nf][0] = -1e9f;
                if (c0 + 1 > row0) Sf[nf][1] = -1e9f;
                if (c0 > row1)     Sf[nf][2] = -1e9f;
                if (c0 + 1 > row1) Sf[nf][3] = -1e9f;
            }
        }

        float rm0 = -INFINITY, rm1 = -INFINITY;
#pragma unroll
        for (int nf = 0; nf < 8; nf++) {
            rm0 = fmaxf(rm0, fmaxf(Sf[nf][0], Sf[nf][1]));
            rm1 = fmaxf(rm1, fmaxf(Sf[nf][2], Sf[nf][3]));
        }
        rm0 = fmaxf(rm0, __shfl_xor_sync(0xffffffffu, rm0, 1));
        rm0 = fmaxf(rm0, __shfl_xor_sync(0xffffffffu, rm0, 2));
        rm1 = fmaxf(rm1, __shfl_xor_sync(0xffffffffu, rm1, 1));
        rm1 = fmaxf(rm1, __shfl_xor_sync(0xffffffffu, rm1, 2));

        const float mn0 = fmaxf(m_i[0], rm0);
        const float mn1 = fmaxf(m_i[1], rm1);
        const float corr0 = ex2(m_i[0] - mn0);
        const float corr1 = ex2(m_i[1] - mn1);
        m_i[0] = mn0; m_i[1] = mn1;

        uint32_t pa[8][4];
        float ps0 = 0.f, ps1 = 0.f;
#pragma unroll
        for (int nf = 0; nf < 8; nf++) {
            float p0 = ex2(Sf[nf][0] - mn0);
            float p1 = ex2(Sf[nf][1] - mn0);
            float p2 = ex2(Sf[nf][2] - mn1);
            float p3 = ex2(Sf[nf][3] - mn1);
            ps0 += p0 + p1;
            ps1 += p2 + p3;
            pa[nf][0] = f2tf(p0); pa[nf][1] = f2tf(p2);
            pa[nf][2] = f2tf(p1); pa[nf][3] = f2tf(p3);
        }
        ps0 += __shfl_xor_sync(0xffffffffu, ps0, 1);
        ps0 += __shfl_xor_sync(0xffffffffu, ps0, 2);
        ps1 += __shfl_xor_sync(0xffffffffu, ps1, 1);
        ps1 += __shfl_xor_sync(0xffffffffu, ps1, 2);
        l_i[0] = l_i[0] * corr0 + ps0;
        l_i[1] = l_i[1] * corr1 + ps1;

#pragma unroll
        for (int nf = 0; nf < 8; nf++) {
            Of[nf][0] *= corr0; Of[nf][1] *= corr0;
            Of[nf][2] *= corr1; Of[nf][3] *= corr1;
        }

#pragma unroll
        for (int pc = 0; pc < 8; pc++) {
#pragma unroll
            for (int onf = 0; onf < 8; onf++) {
                uint2 vv = *(const uint2*)(sV + ((onf << 3) + g) * FS + (pc << 3) + 2 * t);
                uint32_t bfr[2] = { vv.x, vv.y };
                mma_tf32(Of[onf], pa[pc], bfr);
            }
        }
        cur ^= 1;
    }

    // normalize + write g_attn as tf32 + k-interleaved (for out-proj GEMM)
    const float inv0 = 1.f / l_i[0];
    const float inv1 = 1.f / l_i[1];
    const int row0 = q0 + mrow + g;
    const int row1 = row0 + 8;
    const int pc0 = ((t & 1) << 2) | (t >> 1);   // phys(2t): {0,4,1,5}
#pragma unroll
    for (int nf = 0; nf < 8; nf++) {
        const int basec = h * HD_ + (nf << 3);
        g_attn[(size_t)(b * L_ + row0) * D_ + basec + pc0]     = f2tf_f(Of[nf][0] * inv0);
        g_attn[(size_t)(b * L_ + row0) * D_ + basec + pc0 + 2] = f2tf_f(Of[nf][1] * inv0);
        g_attn[(size_t)(b * L_ + row1) * D_ + basec + pc0]     = f2tf_f(Of[nf][2] * inv1);
        g_attn[(size_t)(b * L_ + row1) * D_ + basec + pc0 + 2] = f2tf_f(Of[nf][3] * inv1);
    }
}

// ---------------- launch ----------------------------------------------------
extern "C" void kernel_launch(void* const* d_in, const int* in_sizes, int n_in,
                              void* d_out, int out_size)
{
    const float* q_in = (const float*)d_in[0];
    const float* k_in = (const float*)d_in[1];
    // d_in[2] = v_in (unused by reference), d_in[3] = mask (tril, hardcoded causal)
    const float* rope = (const float*)d_in[4];
    const float* Wq   = (const float*)d_in[5];
    const float* bq   = (const float*)d_in[6];
    const float* Wkv  = (const float*)d_in[7];
    const float* bkv  = (const float*)d_in[8];
    const float* Wp   = (const float*)d_in[9];
    const float* bp   = (const float*)d_in[10];
    float* out = (float*)d_out;

    float *qa, *ka, *wq, *wkv, *wp;
    cudaGetSymbolAddress((void**)&qa,   g_qa);
    cudaGetSymbolAddress((void**)&ka,   g_ka);
    cudaGetSymbolAddress((void**)&wq,   g_wq);
    cudaGetSymbolAddress((void**)&wkv,  g_wkv);
    cudaGetSymbolAddress((void**)&wp,   g_wp);

    // 0) pre-convert inputs/weights to tf32 + k-interleave
    conv_a_kernel<<<dim3(BL_ * D_ / 8 / 256, 2), 256>>>(q_in, qa, k_in, ka);
    conv_w_kernel<<<(D_ * D_ * 4) / 4 / 256, 256>>>(Wq, wq, Wkv, wkv, Wp, wp);

    cudaFuncSetAttribute(gemm_qkv_kernel, cudaFuncAttributeMaxDynamicSharedMemorySize, GSMEM);
    cudaFuncSetAttribute(gemm_out_kernel, cudaFuncAttributeMaxDynamicSharedMemorySize, GSMEM);

    // 1+2) Q and KV projections + fused RoPE/split/V-transpose
    gemm_qkv_kernel<<<1536, 256, GSMEM>>>(bq, bkv, rope);
    // 3) causal flash attention
    cudaFuncSetAttribute(flash_tc_kernel, cudaFuncAttributeMaxDynamicSharedMemorySize, FSMEM);
    flash_tc_kernel<<<dim3(BH_, L_ / 64), 128, FSMEM>>>();
    // 4) output projection
    gemm_out_kernel<<<512, 256, GSMEM>>>(bp, out);
}